// round 12
// baseline (speedup 1.0000x reference)
#include <cuda_runtime.h>

#define S_NODES 8192
#define NN      8384
#define CH      128
#define BB      2
#define EE      262144
#define CAP     96            // bucket capacity per node per CSR type

// ---------------- scratch (device globals; no allocation allowed) -----------
__device__ float  g_h0[BB * NN * CH];
__device__ float  g_h1[BB * NN * CH];
__device__ float  g_qA[BB * NN];
__device__ float  g_qB[BB * NN];
__device__ float2 g_pdA[BB * NN];        // (p, dinvI) packed per node
__device__ float2 g_pdB[BB * NN];
__device__ float  g_dinvI[BB * NN];      // gcn norm: rsqrt(intra_in_deg + 1)
__device__ float  g_dinvX[BB * NN];      // inter: 1/deg or 0
__device__ int    g_cntI[BB * NN];
__device__ int    g_cntX[BB * NN];
__device__ int    g_bI[BB * NN * CAP];   // intra src buckets
__device__ int    g_bX[BB * NN * CAP];   // inter src buckets

__device__ __forceinline__ float tanh_fast(float z) {
    float az = fabsf(z);
    float e  = __expf(2.0f * az);
    float r  = 1.0f - 2.0f / (e + 1.0f);
    return copysignf(r, z);
}

// packed f32x2 helpers (sm_103a; ptxas emits FFMA2 only via PTX f32x2)
__device__ __forceinline__ unsigned long long pack_dup(float c) {
    unsigned long long r;
    unsigned int cb = __float_as_uint(c);
    asm("mov.b64 %0, {%1, %1};" : "=l"(r) : "r"(cb));
    return r;
}
__device__ __forceinline__ void fma_x2(unsigned long long& d,
                                       unsigned long long a,
                                       unsigned long long b) {
    asm("fma.rn.f32x2 %0, %1, %2, %0;" : "+l"(d) : "l"(a), "l"(b));
}
__device__ __forceinline__ float2 unpack_x2(unsigned long long v) {
    unsigned int lo, hi;
    asm("mov.b64 {%0, %1}, %2;" : "=r"(lo), "=r"(hi) : "l"(v));
    return make_float2(__uint_as_float(lo), __uint_as_float(hi));
}

// ---------------- bucket build ---------------------------------------------
__global__ void k_zero() {
    int i = blockIdx.x * blockDim.x + threadIdx.x;
    if (i < BB * NN) { g_cntI[i] = 0; g_cntX[i] = 0; }
}

// 4 edges per thread via int4 loads -> 4 independent atomics in flight
__global__ void k_scatter(const int* __restrict__ ei) {
    int i = blockIdx.x * blockDim.x + threadIdx.x;
    if (i >= BB * (EE / 4)) return;
    int b = i / (EE / 4), e4 = i - b * (EE / 4);
    const int4* sp = (const int4*)(ei + b * 2 * EE);
    const int4* dp = (const int4*)(ei + b * 2 * EE + EE);
    int4 s = sp[e4];
    int4 d = dp[e4];
    int bNN = b * NN;
    #pragma unroll
    for (int k = 0; k < 4; k++) {
        int ss = (&s.x)[k];
        int dd = (&d.x)[k];
        int dn = bNN + dd;
        bool intra = (ss < S_NODES) == (dd < S_NODES);
        if (intra) {
            int pos = atomicAdd(&g_cntI[dn], 1);
            if (pos < CAP) g_bI[dn * CAP + pos] = ss;
        } else {
            int pos = atomicAdd(&g_cntX[dn], 1);
            if (pos < CAP) g_bX[dn * CAP + pos] = ss;
        }
    }
}

// ---------------- prep: dinv + initial dots + bucket sort ------------------
// warp roles: [0, BB*NN) = dots/dinv; [BB*NN, 3*BB*NN) = sort (intra then inter)
__global__ void k_prep(const float* __restrict__ x,
                       float* __restrict__ qout, float2* __restrict__ pdout,
                       const float* __restrict__ WaS, const float* __restrict__ WbS,
                       const float* __restrict__ WaT, const float* __restrict__ WbT) {
    int t = blockIdx.x * blockDim.x + threadIdx.x;
    int wg = t >> 5, lane = t & 31;
    if (wg >= 3 * BB * NN) return;

    if (wg < BB * NN) {            // ---- dots + dinv role ----
        int w = wg;
        int v = w % NN;
        int cI = g_cntI[w];
        int cX = g_cntX[w];
        float dI = rsqrtf((float)(cI + 1));
        float dX = (cX > 0) ? (1.0f / (float)cX) : 0.0f;
        if (lane == 0) { g_dinvI[w] = dI; g_dinvX[w] = dX; }
        const float* Wa = (v < S_NODES) ? WaS : WaT;
        const float* Wb = (v < S_NODES) ? WbS : WbT;
        float4 xv = ((const float4*)x)[w * 32 + lane];
        float4 wa = ((const float4*)Wa)[lane];
        float4 wb = ((const float4*)Wb)[lane];
        float qs = xv.x * wa.x + xv.y * wa.y + xv.z * wa.z + xv.w * wa.w;
        float ps = xv.x * wb.x + xv.y * wb.y + xv.z * wb.z + xv.w * wb.w;
        #pragma unroll
        for (int o = 16; o > 0; o >>= 1) {
            qs += __shfl_xor_sync(0xffffffffu, qs, o);
            ps += __shfl_xor_sync(0xffffffffu, ps, o);
        }
        if (lane == 0) { qout[w] = qs; pdout[w] = make_float2(ps, dI); }
    } else {                        // ---- sort role (bitonic, warp per node) ----
        int m = wg - BB * NN;
        bool intra = m < BB * NN;
        int n = intra ? m : m - BB * NN;     // global node index
        int* bucket = (intra ? g_bI : g_bX) + n * CAP;
        int cnt = intra ? g_cntI[n] : g_cntX[n];
        int len = min(cnt, CAP);
        if (len <= 1) return;
        if (len <= 64) {
            int r0 = (lane < len)      ? bucket[lane]      : 0x7fffffff;
            int r1 = (32 + lane < len) ? bucket[32 + lane] : 0x7fffffff;
            for (int k = 2; k <= 64; k <<= 1) {
                for (int j = k >> 1; j > 0; j >>= 1) {
                    if (j == 32) {
                        int lo = min(r0, r1), hi = max(r0, r1);
                        r0 = lo; r1 = hi;
                    } else {
                        int o0 = __shfl_xor_sync(0xffffffffu, r0, j);
                        int o1 = __shfl_xor_sync(0xffffffffu, r1, j);
                        bool bit = (lane & j) != 0;
                        bool up0 = ((lane & k) == 0);
                        bool up1 = (((lane + 32) & k) == 0);
                        r0 = (bit != up0) ? min(r0, o0) : max(r0, o0);
                        r1 = (bit != up1) ? min(r1, o1) : max(r1, o1);
                    }
                }
            }
            if (lane < len)      bucket[lane]      = r0;
            if (32 + lane < len) bucket[32 + lane] = r1;
        } else if (lane == 0) {      // astronomically rare
            for (int i = 1; i < len; i++) {
                int key = bucket[i]; int j = i - 1;
                while (j >= 0 && bucket[j] > key) { bucket[j + 1] = bucket[j]; j--; }
                bucket[j + 1] = key;
            }
        }
    }
}

// ---------------- gather: TWO warps per node -------------------------------
// Warp pair (h=0,1) splits the edge list at half=len/2 (fixed -> deterministic:
// total = sum(first half) + sum(second half), each serial in sorted order).
// Each warp stages coefs for its own range (lane-parallel), accumulates with
// f32x2 packed FMA; warp1 deposits partials in smem; warp0 combines + epilogue.
template <bool INTRA, bool RELU, bool DOTS>
__global__ void k_gather(const float* __restrict__ xin, float* __restrict__ xout,
                         const float* __restrict__ qin, const float2* __restrict__ pdin,
                         float* __restrict__ qout, float2* __restrict__ pdout,
                         const float* __restrict__ WaS, const float* __restrict__ WbS,
                         const float* __restrict__ WaT, const float* __restrict__ WbT) {
    __shared__ int2   s_sc[4][CAP];       // 4 nodes/block * 96 slots * 8B = 3KB
    __shared__ float4 s_part[4][32];      // warp1 partials: 2KB
    int t = blockIdx.x * blockDim.x + threadIdx.x;
    int gw = t >> 5, lane = t & 31;
    int w = gw >> 1, h = gw & 1;          // node, half-index
    if (w >= BB * NN) return;
    int nl = (threadIdx.x >> 6);          // node slot in block (0..3)
    int b = w / NN;
    int v = w - b * NN;
    int bNN = b * NN;

    float qv = qin[w];
    float dv = INTRA ? g_dinvI[w] : g_dinvX[w];
    int len = min(INTRA ? g_cntI[w] : g_cntX[w], CAP);
    int half = len >> 1;
    int beg = h ? half : 0;
    int end = h ? len  : half;
    const int* __restrict__ bucket = (INTRA ? g_bI : g_bX) + w * CAP;

    // phase 1: lane-parallel coefficients for this warp's own range
    for (int pos = beg + lane; pos < end; pos += 32) {
        int s = bucket[pos];
        float2 ps = pdin[bNN + s];
        float z = tanh_fast(qv + ps.x);
        float c = INTRA ? z * dv * ps.y : z * dv;
        s_sc[nl][pos] = make_int2(s, __float_as_int(c));
    }
    __syncwarp();

    // phase 2: serial accumulate of this warp's range (fixed order)
    const ulonglong2* __restrict__ x2 = (const ulonglong2*)xin;  // 16B per lane
    unsigned long long acc01 = 0, acc23 = 0;

    int e = beg;
    for (; e + 4 <= end; e += 4) {
        int2 s0 = s_sc[nl][e],     s1 = s_sc[nl][e + 1];
        int2 s2 = s_sc[nl][e + 2], s3 = s_sc[nl][e + 3];
        ulonglong2 x0 = x2[(bNN + s0.x) * 32 + lane];
        ulonglong2 x1 = x2[(bNN + s1.x) * 32 + lane];
        ulonglong2 xx2 = x2[(bNN + s2.x) * 32 + lane];
        ulonglong2 x3 = x2[(bNN + s3.x) * 32 + lane];
        unsigned long long c0 = pack_dup(__int_as_float(s0.y));
        unsigned long long c1 = pack_dup(__int_as_float(s1.y));
        unsigned long long c2 = pack_dup(__int_as_float(s2.y));
        unsigned long long c3 = pack_dup(__int_as_float(s3.y));
        fma_x2(acc01, c0, x0.x);  fma_x2(acc23, c0, x0.y);
        fma_x2(acc01, c1, x1.x);  fma_x2(acc23, c1, x1.y);
        fma_x2(acc01, c2, xx2.x); fma_x2(acc23, c2, xx2.y);
        fma_x2(acc01, c3, x3.x);  fma_x2(acc23, c3, x3.y);
    }
    for (; e < end; e++) {
        int2 se = s_sc[nl][e];
        ulonglong2 xe = x2[(bNN + se.x) * 32 + lane];
        unsigned long long ce = pack_dup(__int_as_float(se.y));
        fma_x2(acc01, ce, xe.x); fma_x2(acc23, ce, xe.y);
    }

    float2 a01 = unpack_x2(acc01);
    float2 a23 = unpack_x2(acc23);

    if (h == 1) {  // second-half warp deposits its partial
        s_part[nl][lane] = make_float4(a01.x, a01.y, a23.x, a23.y);
    }
    __syncthreads();
    if (h == 1) return;

    // warp0: combine partials (fixed order), then epilogue
    float4 p1 = s_part[nl][lane];
    float4 acc;
    acc.x = a01.x + p1.x; acc.y = a01.y + p1.y;
    acc.z = a23.x + p1.z; acc.w = a23.y + p1.w;

    float4 xv = ((const float4*)xin)[w * 32 + lane];
    if (INTRA) {  // self loop: alpha_self = tanh(q+p), norm = 1/deg = dinv^2
        float cs = tanh_fast(qv + pdin[w].x) * dv * dv;
        acc.x += cs * xv.x; acc.y += cs * xv.y;
        acc.z += cs * xv.z; acc.w += cs * xv.w;
    }
    float4 o;
    o.x = xv.x + acc.x; o.y = xv.y + acc.y;
    o.z = xv.z + acc.z; o.w = xv.w + acc.w;
    if (RELU) {
        o.x = fmaxf(o.x, 0.f); o.y = fmaxf(o.y, 0.f);
        o.z = fmaxf(o.z, 0.f); o.w = fmaxf(o.w, 0.f);
    }
    ((float4*)xout)[w * 32 + lane] = o;

    if (DOTS) {  // q,p for the NEXT pass from the freshly computed output
        const float* Wa = (v < S_NODES) ? WaS : WaT;
        const float* Wb = (v < S_NODES) ? WbS : WbT;
        float4 wa = ((const float4*)Wa)[lane];
        float4 wb = ((const float4*)Wb)[lane];
        float qs = o.x * wa.x + o.y * wa.y + o.z * wa.z + o.w * wa.w;
        float ps = o.x * wb.x + o.y * wb.y + o.z * wb.z + o.w * wb.w;
        #pragma unroll
        for (int off = 16; off > 0; off >>= 1) {
            qs += __shfl_xor_sync(0xffffffffu, qs, off);
            ps += __shfl_xor_sync(0xffffffffu, ps, off);
        }
        if (lane == 0) { qout[w] = qs; pdout[w] = make_float2(ps, g_dinvI[w]); }
    }
}

// ---------------- launch ---------------------------------------------------
extern "C" void kernel_launch(void* const* d_in, const int* in_sizes, int n_in,
                              void* d_out, int out_size) {
    const float* x   = (const float*)d_in[0];
    const int*   ei  = (const int*)d_in[1];
    const float* Wss = (const float*)d_in[2];
    const float* Wtt = (const float*)d_in[3];
    const float* Wst = (const float*)d_in[4];
    const float* Wts = (const float*)d_in[5];
    float* out = (float*)d_out;

    float *h0, *h1, *qA, *qB;
    float2 *pdA, *pdB;
    cudaGetSymbolAddress((void**)&h0,  g_h0);
    cudaGetSymbolAddress((void**)&h1,  g_h1);
    cudaGetSymbolAddress((void**)&qA,  g_qA);
    cudaGetSymbolAddress((void**)&qB,  g_qB);
    cudaGetSymbolAddress((void**)&pdA, g_pdA);
    cudaGetSymbolAddress((void**)&pdB, g_pdB);

    // bucket CSR build (depends only on edge_index; recomputed every call)
    k_zero<<<(BB * NN + 255) / 256, 256>>>();
    k_scatter<<<(BB * (EE / 4) + 255) / 256, 256>>>(ei);

    // prep: dinv + initial dots (intra L0 weights) + bucket sort
    k_prep<<<(3 * BB * NN * 32 + 255) / 256, 256>>>(
        x, qA, pdA, Wss, Wss + 128, Wtt, Wtt + 128);

    int ng = (BB * NN * 2 * 32 + 255) / 256;   // TWO warps per node

    // pass 0: intra L0, relu; fused dots for pass 1 (inter L0) -> set B
    k_gather<true, true, true><<<ng, 256>>>(
        x, h0, qA, pdA, qB, pdB, Wts, Wst + 128, Wst, Wts + 128);

    // pass 1: inter L0, relu; fused dots for pass 2 (intra L1) -> set A
    k_gather<false, true, true><<<ng, 256>>>(
        h0, h1, qB, pdB, qA, pdA, Wss + 256, Wss + 384, Wtt + 256, Wtt + 384);

    // pass 2: intra L1, relu; fused dots for pass 3 (inter L1) -> set B
    k_gather<true, true, true><<<ng, 256>>>(
        h1, h0, qA, pdA, qB, pdB, Wts + 256, Wst + 384, Wst + 256, Wts + 384);

    // pass 3: inter L1, no relu, write straight to d_out
    k_gather<false, false, false><<<ng, 256>>>(
        h0, out, qB, pdB, nullptr, nullptr, nullptr, nullptr, nullptr, nullptr);
}

// round 16
// speedup vs baseline: 1.1324x; 1.1324x over previous
#include <cuda_runtime.h>
#include <cuda_fp16.h>

#define S_NODES 8192
#define NN      8384
#define CH      128
#define BB      2
#define EE      262144
#define CAP     96            // bucket capacity per node per CSR type

// ---------------- scratch (device globals; no allocation allowed) -----------
__device__ float  g_h0[BB * NN * CH];
__device__ float  g_h1[BB * NN * CH];
__device__ __half g_hxA[BB * NN * CH];   // fp16 shadow of features (gather operand)
__device__ __half g_hxB[BB * NN * CH];
__device__ float  g_qA[BB * NN];
__device__ float  g_qB[BB * NN];
__device__ float2 g_pdA[BB * NN];        // (p, dinvI) packed per node
__device__ float2 g_pdB[BB * NN];
__device__ float  g_dinvI[BB * NN];      // gcn norm: rsqrt(intra_in_deg + 1)
__device__ float  g_dinvX[BB * NN];      // inter: 1/deg or 0
__device__ int    g_cntI[BB * NN];
__device__ int    g_cntX[BB * NN];
__device__ int    g_bI[BB * NN * CAP];   // intra src buckets
__device__ int    g_bX[BB * NN * CAP];   // inter src buckets

__device__ __forceinline__ float tanh_fast(float z) {
    float az = fabsf(z);
    float e  = __expf(2.0f * az);
    float r  = 1.0f - 2.0f / (e + 1.0f);
    return copysignf(r, z);
}

// bit-cast helpers (no __half2_as_uint intrinsic exists)
__device__ __forceinline__ unsigned int h2_to_u32(__half2 h) {
    return *reinterpret_cast<unsigned int*>(&h);
}
__device__ __forceinline__ __half2 u32_to_h2(unsigned int u) {
    return *reinterpret_cast<__half2*>(&u);
}

// ---------------- bucket build ---------------------------------------------
__global__ void k_zero() {
    int i = blockIdx.x * blockDim.x + threadIdx.x;
    if (i < BB * NN) { g_cntI[i] = 0; g_cntX[i] = 0; }
}

// 4 edges per thread via int4 loads -> 4 independent atomics in flight
__global__ void k_scatter(const int* __restrict__ ei) {
    int i = blockIdx.x * blockDim.x + threadIdx.x;
    if (i >= BB * (EE / 4)) return;
    int b = i / (EE / 4), e4 = i - b * (EE / 4);
    const int4* sp = (const int4*)(ei + b * 2 * EE);
    const int4* dp = (const int4*)(ei + b * 2 * EE + EE);
    int4 s = sp[e4];
    int4 d = dp[e4];
    int bNN = b * NN;
    #pragma unroll
    for (int k = 0; k < 4; k++) {
        int ss = (&s.x)[k];
        int dd = (&d.x)[k];
        int dn = bNN + dd;
        bool intra = (ss < S_NODES) == (dd < S_NODES);
        if (intra) {
            int pos = atomicAdd(&g_cntI[dn], 1);
            if (pos < CAP) g_bI[dn * CAP + pos] = ss;
        } else {
            int pos = atomicAdd(&g_cntX[dn], 1);
            if (pos < CAP) g_bX[dn * CAP + pos] = ss;
        }
    }
}

// ---------------- prep: dinv + initial dots + fp16 copy + bucket sort ------
// warp roles: [0, BB*NN) = dots/dinv/copy; [BB*NN, 3*BB*NN) = sort
__global__ void k_prep(const float* __restrict__ x,
                       float* __restrict__ qout, float2* __restrict__ pdout,
                       uint2* __restrict__ hxout,
                       const float* __restrict__ WaS, const float* __restrict__ WbS,
                       const float* __restrict__ WaT, const float* __restrict__ WbT) {
    int t = blockIdx.x * blockDim.x + threadIdx.x;
    int wg = t >> 5, lane = t & 31;
    if (wg >= 3 * BB * NN) return;

    if (wg < BB * NN) {            // ---- dots + dinv + fp16 copy role ----
        int w = wg;
        int v = w % NN;
        int cI = g_cntI[w];
        int cX = g_cntX[w];
        float dI = rsqrtf((float)(cI + 1));
        float dX = (cX > 0) ? (1.0f / (float)cX) : 0.0f;
        if (lane == 0) { g_dinvI[w] = dI; g_dinvX[w] = dX; }
        const float* Wa = (v < S_NODES) ? WaS : WaT;
        const float* Wb = (v < S_NODES) ? WbS : WbT;
        float4 xv = ((const float4*)x)[w * 32 + lane];
        uint2 hv;
        hv.x = h2_to_u32(__floats2half2_rn(xv.x, xv.y));
        hv.y = h2_to_u32(__floats2half2_rn(xv.z, xv.w));
        hxout[w * 32 + lane] = hv;
        float4 wa = ((const float4*)Wa)[lane];
        float4 wb = ((const float4*)Wb)[lane];
        float qs = xv.x * wa.x + xv.y * wa.y + xv.z * wa.z + xv.w * wa.w;
        float ps = xv.x * wb.x + xv.y * wb.y + xv.z * wb.z + xv.w * wb.w;
        #pragma unroll
        for (int o = 16; o > 0; o >>= 1) {
            qs += __shfl_xor_sync(0xffffffffu, qs, o);
            ps += __shfl_xor_sync(0xffffffffu, ps, o);
        }
        if (lane == 0) { qout[w] = qs; pdout[w] = make_float2(ps, dI); }
    } else {                        // ---- sort role (bitonic, warp per node) ----
        int m = wg - BB * NN;
        bool intra = m < BB * NN;
        int n = intra ? m : m - BB * NN;     // global node index
        int* bucket = (intra ? g_bI : g_bX) + n * CAP;
        int cnt = intra ? g_cntI[n] : g_cntX[n];
        int len = min(cnt, CAP);
        if (len <= 1) return;
        if (len <= 64) {
            int r0 = (lane < len)      ? bucket[lane]      : 0x7fffffff;
            int r1 = (32 + lane < len) ? bucket[32 + lane] : 0x7fffffff;
            for (int k = 2; k <= 64; k <<= 1) {
                for (int j = k >> 1; j > 0; j >>= 1) {
                    if (j == 32) {
                        int lo = min(r0, r1), hi = max(r0, r1);
                        r0 = lo; r1 = hi;
                    } else {
                        int o0 = __shfl_xor_sync(0xffffffffu, r0, j);
                        int o1 = __shfl_xor_sync(0xffffffffu, r1, j);
                        bool bit = (lane & j) != 0;
                        bool up0 = ((lane & k) == 0);
                        bool up1 = (((lane + 32) & k) == 0);
                        r0 = (bit != up0) ? min(r0, o0) : max(r0, o0);
                        r1 = (bit != up1) ? min(r1, o1) : max(r1, o1);
                    }
                }
            }
            if (lane < len)      bucket[lane]      = r0;
            if (32 + lane < len) bucket[32 + lane] = r1;
        } else if (lane == 0) {      // astronomically rare
            for (int i = 1; i < len; i++) {
                int key = bucket[i]; int j = i - 1;
                while (j >= 0 && bucket[j] > key) { bucket[j + 1] = bucket[j]; j--; }
                bucket[j + 1] = key;
            }
        }
    }
}

// ---------------- gather: warp per node, fp16 operand ----------------------
// Phase 1 (lane-parallel): (src, coef) into smem.
// Phase 2 (serial, fixed order): accumulate fp16 rows (LDG.64/lane) in fp32.
template <bool INTRA, bool RELU, bool DOTS, bool WRITEH>
__global__ void k_gather(const float* __restrict__ xin, float* __restrict__ xout,
                         const uint2* __restrict__ hxin, uint2* __restrict__ hxout,
                         const float* __restrict__ qin, const float2* __restrict__ pdin,
                         float* __restrict__ qout, float2* __restrict__ pdout,
                         const float* __restrict__ WaS, const float* __restrict__ WbS,
                         const float* __restrict__ WaT, const float* __restrict__ WbT) {
    __shared__ int2 s_sc[8][CAP];          // 8 warps/block * 96 slots * 8B = 6KB
    int t = blockIdx.x * blockDim.x + threadIdx.x;
    int w = t >> 5, lane = t & 31;
    if (w >= BB * NN) return;
    int wl = threadIdx.x >> 5;
    int b = w / NN;
    int v = w - b * NN;
    int bNN = b * NN;

    float qv = qin[w];
    float dv = INTRA ? g_dinvI[w] : g_dinvX[w];
    int len = min(INTRA ? g_cntI[w] : g_cntX[w], CAP);
    const int* __restrict__ bucket = (INTRA ? g_bI : g_bX) + w * CAP;

    // phase 1: lane-parallel coefficients into smem
    for (int pos = lane; pos < len; pos += 32) {
        int s = bucket[pos];
        float2 ps = pdin[bNN + s];
        float z = tanh_fast(qv + ps.x);
        float c = INTRA ? z * dv * ps.y : z * dv;
        s_sc[wl][pos] = make_int2(s, __float_as_int(c));
    }
    __syncwarp();

    // phase 2: serial accumulate (fixed sorted order -> deterministic)
    float4 acc = make_float4(0.f, 0.f, 0.f, 0.f);

    int e = 0;
    for (; e + 4 <= len; e += 4) {
        int2 s0 = s_sc[wl][e],     s1 = s_sc[wl][e + 1];
        int2 s2 = s_sc[wl][e + 2], s3 = s_sc[wl][e + 3];
        uint2 h0 = hxin[(bNN + s0.x) * 32 + lane];
        uint2 h1 = hxin[(bNN + s1.x) * 32 + lane];
        uint2 h2 = hxin[(bNN + s2.x) * 32 + lane];
        uint2 h3 = hxin[(bNN + s3.x) * 32 + lane];
        float c0 = __int_as_float(s0.y), c1 = __int_as_float(s1.y);
        float c2 = __int_as_float(s2.y), c3 = __int_as_float(s3.y);
        float2 l0 = __half22float2(u32_to_h2(h0.x));
        float2 m0 = __half22float2(u32_to_h2(h0.y));
        float2 l1 = __half22float2(u32_to_h2(h1.x));
        float2 m1 = __half22float2(u32_to_h2(h1.y));
        float2 l2 = __half22float2(u32_to_h2(h2.x));
        float2 m2 = __half22float2(u32_to_h2(h2.y));
        float2 l3 = __half22float2(u32_to_h2(h3.x));
        float2 m3 = __half22float2(u32_to_h2(h3.y));
        acc.x += c0 * l0.x; acc.y += c0 * l0.y; acc.z += c0 * m0.x; acc.w += c0 * m0.y;
        acc.x += c1 * l1.x; acc.y += c1 * l1.y; acc.z += c1 * m1.x; acc.w += c1 * m1.y;
        acc.x += c2 * l2.x; acc.y += c2 * l2.y; acc.z += c2 * m2.x; acc.w += c2 * m2.y;
        acc.x += c3 * l3.x; acc.y += c3 * l3.y; acc.z += c3 * m3.x; acc.w += c3 * m3.y;
    }
    for (; e < len; e++) {
        int2 se = s_sc[wl][e];
        uint2 he = hxin[(bNN + se.x) * 32 + lane];
        float ce = __int_as_float(se.y);
        float2 lo = __half22float2(u32_to_h2(he.x));
        float2 hi = __half22float2(u32_to_h2(he.y));
        acc.x += ce * lo.x; acc.y += ce * lo.y;
        acc.z += ce * hi.x; acc.w += ce * hi.y;
    }

    float4 xv = ((const float4*)xin)[w * 32 + lane];
    if (INTRA) {  // self loop in fp32: alpha_self = tanh(q+p), norm = dinv^2
        float cs = tanh_fast(qv + pdin[w].x) * dv * dv;
        acc.x += cs * xv.x; acc.y += cs * xv.y;
        acc.z += cs * xv.z; acc.w += cs * xv.w;
    }
    float4 o;
    o.x = xv.x + acc.x; o.y = xv.y + acc.y;
    o.z = xv.z + acc.z; o.w = xv.w + acc.w;
    if (RELU) {
        o.x = fmaxf(o.x, 0.f); o.y = fmaxf(o.y, 0.f);
        o.z = fmaxf(o.z, 0.f); o.w = fmaxf(o.w, 0.f);
    }
    ((float4*)xout)[w * 32 + lane] = o;
    if (WRITEH) {
        uint2 ho;
        ho.x = h2_to_u32(__floats2half2_rn(o.x, o.y));
        ho.y = h2_to_u32(__floats2half2_rn(o.z, o.w));
        hxout[w * 32 + lane] = ho;
    }

    if (DOTS) {  // q,p for the NEXT pass from the freshly computed output
        const float* Wa = (v < S_NODES) ? WaS : WaT;
        const float* Wb = (v < S_NODES) ? WbS : WbT;
        float4 wa = ((const float4*)Wa)[lane];
        float4 wb = ((const float4*)Wb)[lane];
        float qs = o.x * wa.x + o.y * wa.y + o.z * wa.z + o.w * wa.w;
        float ps = o.x * wb.x + o.y * wb.y + o.z * wb.z + o.w * wb.w;
        #pragma unroll
        for (int off = 16; off > 0; off >>= 1) {
            qs += __shfl_xor_sync(0xffffffffu, qs, off);
            ps += __shfl_xor_sync(0xffffffffu, ps, off);
        }
        if (lane == 0) { qout[w] = qs; pdout[w] = make_float2(ps, g_dinvI[w]); }
    }
}

// ---------------- launch ---------------------------------------------------
extern "C" void kernel_launch(void* const* d_in, const int* in_sizes, int n_in,
                              void* d_out, int out_size) {
    const float* x   = (const float*)d_in[0];
    const int*   ei  = (const int*)d_in[1];
    const float* Wss = (const float*)d_in[2];
    const float* Wtt = (const float*)d_in[3];
    const float* Wst = (const float*)d_in[4];
    const float* Wts = (const float*)d_in[5];
    float* out = (float*)d_out;

    float *h0, *h1, *qA, *qB;
    float2 *pdA, *pdB;
    uint2 *hxA, *hxB;
    cudaGetSymbolAddress((void**)&h0,  g_h0);
    cudaGetSymbolAddress((void**)&h1,  g_h1);
    cudaGetSymbolAddress((void**)&qA,  g_qA);
    cudaGetSymbolAddress((void**)&qB,  g_qB);
    cudaGetSymbolAddress((void**)&pdA, g_pdA);
    cudaGetSymbolAddress((void**)&pdB, g_pdB);
    cudaGetSymbolAddress((void**)&hxA, g_hxA);
    cudaGetSymbolAddress((void**)&hxB, g_hxB);

    // bucket CSR build (depends only on edge_index; recomputed every call)
    k_zero<<<(BB * NN + 255) / 256, 256>>>();
    k_scatter<<<(BB * (EE / 4) + 255) / 256, 256>>>(ei);

    // prep: dinv + initial dots (intra L0 weights) + fp16 copy + bucket sort
    k_prep<<<(3 * BB * NN * 32 + 255) / 256, 256>>>(
        x, qA, pdA, hxA, Wss, Wss + 128, Wtt, Wtt + 128);

    int ng = (BB * NN * 32 + 255) / 256;   // one warp per node

    // pass 0: intra L0, relu; fused dots for pass 1 (inter L0) -> set B, hxB
    k_gather<true, true, true, true><<<ng, 256>>>(
        x, h0, hxA, hxB, qA, pdA, qB, pdB,
        Wts, Wst + 128, Wst, Wts + 128);

    // pass 1: inter L0, relu; fused dots for pass 2 (intra L1) -> set A, hxA
    k_gather<false, true, true, true><<<ng, 256>>>(
        h0, h1, hxB, hxA, qB, pdB, qA, pdA,
        Wss + 256, Wss + 384, Wtt + 256, Wtt + 384);

    // pass 2: intra L1, relu; fused dots for pass 3 (inter L1) -> set B, hxB
    k_gather<true, true, true, true><<<ng, 256>>>(
        h1, h0, hxA, hxB, qA, pdA, qB, pdB,
        Wts + 256, Wst + 384, Wst + 256, Wts + 384);

    // pass 3: inter L1, no relu, write straight to d_out
    k_gather<false, false, false, false><<<ng, 256>>>(
        h0, out, hxB, nullptr, qB, pdB, nullptr, nullptr,
        nullptr, nullptr, nullptr, nullptr);
}